// round 17
// baseline (speedup 1.0000x reference)
#include <cuda_runtime.h>
#include <cuda_fp16.h>
#include <cstdint>
#include <math.h>

#define Bsz 2
#define Lseq 4096
#define DM 768
#define DS 16
#define EE 1536
#define NROWS (Bsz*Lseq)      // 8192
#define HROWS (NROWS/2)       // 4096 per batch
#define KCAT 1600
#define KC_CAT 100            // KCAT/16
#define LN_EPS 1e-5f
#define XD_ZS 4

#define STAGE_BYTES 32768
#define GEMM_SMEM (3 * STAGE_BYTES)

// prep_main: winF then LN rows. 384 threads.
#define PM_WIN   3072
#define PM_TOTAL (PM_WIN + NROWS)

// prep_side regions
#define PS_WOL  1536
#define PS_XPL  (PS_WOL + 3072)
#define PS_WPS  (PS_XPL + 512)
#define PS_WUS2 (PS_WPS + 24)
#define PS_CB   (PS_WUS2 + 2)
#define PS_ZC   (PS_CB + 1024)

// ======================= small PTX helpers ==================================
__device__ __forceinline__ uint32_t smem_u32(const void* p) {
    uint32_t a;
    asm("{ .reg .u64 t; cvta.to.shared.u64 t, %1; cvt.u32.u64 %0, t; }"
        : "=r"(a) : "l"(p));
    return a;
}
__device__ __forceinline__ void cp_async16(uint32_t dst, const void* src) {
    asm volatile("cp.async.cg.shared.global [%0], [%1], 16;"
                 :: "r"(dst), "l"(src) : "memory");
}
__device__ __forceinline__ void cp_commit() {
    asm volatile("cp.async.commit_group;" ::: "memory");
}
template<int N> __device__ __forceinline__ void cp_wait() {
    asm volatile("cp.async.wait_group %0;" :: "n"(N) : "memory");
}
__device__ __forceinline__ void mma_f16(float* c, const uint32_t* a, const uint32_t* b) {
    asm volatile("mma.sync.aligned.m16n8k16.row.col.f32.f16.f16.f32 "
        "{%0,%1,%2,%3}, {%4,%5,%6,%7}, {%8,%9}, {%0,%1,%2,%3};"
        : "+f"(c[0]), "+f"(c[1]), "+f"(c[2]), "+f"(c[3])
        : "r"(a[0]), "r"(a[1]), "r"(a[2]), "r"(a[3]), "r"(b[0]), "r"(b[1]));
}

// ---- fp16 fragment-native layouts (half-element index) ----------------------
__device__ __forceinline__ size_t afh_idx(int r, int k, int KC16) {
    size_t blk = (size_t)((r >> 4) * KC16 + (k >> 4));
    int b32 = (r & 7) * 16 + ((k >> 1) & 3) * 4 + ((r >> 3) & 1) + 2 * ((k >> 3) & 1);
    return blk * 256 + b32 * 2 + (k & 1);
}
__device__ __forceinline__ void afh_inv(int idx, int KC16, int& r, int& k) {
    int blk = idx >> 8;
    int b32 = (idx & 255) >> 1, h = idx & 1;
    r = (blk / KC16) * 16 + ((b32 & 1) << 3) + (b32 >> 4);
    k = ((blk % KC16) << 4) | (((b32 >> 1) & 1) << 3) | (((b32 >> 2) & 3) << 1) | h;
}
__device__ __forceinline__ size_t bfh_idx(int n, int k, int KC16) {
    size_t blk = (size_t)((n >> 3) * KC16 + (k >> 4));
    int b32 = (n & 7) * 8 + ((k >> 1) & 3) * 2 + ((k >> 3) & 1);
    return blk * 128 + b32 * 2 + (k & 1);
}
__device__ __forceinline__ void bfh_inv(int idx, int KC16, int& n, int& k) {
    int blk = idx >> 7;
    int b32 = (idx & 127) >> 1, h = idx & 1;
    n = (blk / KC16) * 8 + (b32 >> 3);
    k = ((blk % KC16) << 4) | ((b32 & 1) << 3) | (((b32 >> 1) & 3) << 1) | h;
}

// ======================= scratch ============================================
__device__ __align__(256) __half g_xn    [NROWS * DM];
__device__ __align__(256) __half g_xin   [NROWS * EE];
__device__ __align__(256) __half g_cat   [NROWS * KCAT];
__device__ __align__(256) float  g_xd    [XD_ZS * NROWS * 32];
__device__ float g_dt [NROWS * DS];
__device__ float g_bt [NROWS * DS];
__device__ float g_bias32[32];
__device__ float g_cbias [DM];
__device__ __align__(256) __half g_winF  [EE * DM];
__device__ __align__(256) __half g_wpsF  [128 * EE];
__device__ __align__(256) __half g_xplF  [EE * DM];
__device__ __align__(256) __half g_wolF  [DM * DM];
__device__ __align__(256) __half g_comboF[(DM/8) * KC_CAT * 128];

// ======================= fp16 mma.sync GEMM (row0-offset capable) ===========
template<int MODE>
__global__ __launch_bounds__(256, 2) void gemm_f16_kernel(
    const __half* __restrict__ Af, int kc16s,
    const __half* __restrict__ Bf,
    const float* __restrict__ bias, void* __restrict__ Cv,
    int ldc, int Ndim, int K, const float* __restrict__ addW,
    size_t zstride, int row0)
{
    extern __shared__ __align__(16) char sm[];
    const int tid = threadIdx.x;
    const int wid = tid >> 5, lane = tid & 31;
    const int wm = wid >> 1, wn = wid & 1;
    const int g = lane >> 2, tg = lane & 3;
    const int KC16 = K >> 4;
    const int NCz = (K >> 6) / gridDim.z;
    const int c0 = blockIdx.z * NCz;
    const int mp0 = (row0 >> 4) + blockIdx.y * 8;
    const int ng0 = blockIdx.x * 16;
    const int m0 = row0 + blockIdx.y * 128, n0 = blockIdx.x * 128;
    const uint32_t smb = smem_u32(sm);

    auto load_chunk = [&](int i) {
        const int c = c0 + i;
        const uint32_t st = (uint32_t)(i % 3) * STAGE_BYTES;
        #pragma unroll
        for (int j = 0; j < 4; j++) {
            int L = tid + 256 * j;
            int pp = L >> 7, qq = (L >> 5) & 3, ll = L & 31;
            const __half* src = Af + ((size_t)(mp0 + pp) * kc16s + 4 * c + qq) * 256 + ll * 8;
            cp_async16(smb + st + (uint32_t)((pp * 4 + qq) * 512 + ll * 16), src);
        }
        #pragma unroll
        for (int j = 0; j < 4; j++) {
            int L = tid + 256 * j;
            int ng = L >> 6, qq = (L >> 4) & 3, ll = L & 15;
            const __half* src = Bf + ((size_t)(ng0 + ng) * KC16 + 4 * c + qq) * 128 + ll * 8;
            cp_async16(smb + st + 16384u + (uint32_t)((ng * 4 + qq) * 256 + ll * 16), src);
        }
        cp_commit();
    };

    float acc[2][8][4];
    #pragma unroll
    for (int mi = 0; mi < 2; mi++)
        #pragma unroll
        for (int ni = 0; ni < 8; ni++)
            #pragma unroll
            for (int q = 0; q < 4; q++) acc[mi][ni][q] = 0.0f;

    load_chunk(0); load_chunk(1);

    const char* stA_w = sm + wm * 4096 + g * 64 + tg * 16;
    const char* stB_w = sm + 16384 + wn * 8192 + g * 32 + tg * 8;

    for (int i = 0; i < NCz; i++) {
        cp_wait<1>();
        __syncthreads();
        if (i + 2 < NCz) load_chunk(i + 2); else cp_commit();

        const char* stA = stA_w + (i % 3) * STAGE_BYTES;
        const char* stB = stB_w + (i % 3) * STAGE_BYTES;

        #pragma unroll
        for (int kb = 0; kb < 4; kb++) {
            uint4 a0 = *(const uint4*)(stA + kb * 512);
            uint4 a1 = *(const uint4*)(stA + 2048 + kb * 512);
            uint2 bq[8];
            #pragma unroll
            for (int ni = 0; ni < 8; ni++)
                bq[ni] = *(const uint2*)(stB + ni * 1024 + kb * 256);
            #pragma unroll
            for (int ni = 0; ni < 8; ni++) {
                mma_f16(acc[0][ni], (const uint32_t*)&a0, (const uint32_t*)&bq[ni]);
                mma_f16(acc[1][ni], (const uint32_t*)&a1, (const uint32_t*)&bq[ni]);
            }
        }
    }

    if (MODE == 2) {
        __half* Cc = (__half*)Cv;
        #pragma unroll
        for (int mi = 0; mi < 2; mi++)
            #pragma unroll
            for (int ni = 0; ni < 8; ni++)
                #pragma unroll
                for (int q = 0; q < 4; q++) {
                    int row = m0 + wm * 32 + mi * 16 + g + ((q >> 1) << 3);
                    int col = n0 + wn * 64 + ni * 8 + tg * 2 + (q & 1);
                    float v = acc[mi][ni][q];
                    if (row >= DM) v += addW[(size_t)row * DM + col];
                    Cc[bfh_idx(col, row, KC_CAT)] = __float2half_rn(v);
                }
    } else {
        const bool ub = (blockIdx.z == 0);
        char* Cz = (char*)Cv + (size_t)blockIdx.z * zstride;
        #pragma unroll
        for (int mi = 0; mi < 2; mi++) {
            const int row = m0 + wm * 32 + mi * 16 + g;
            #pragma unroll
            for (int ni = 0; ni < 8; ni++) {
                const int col = n0 + wn * 64 + ni * 8 + tg * 2;
                if (col < Ndim) {
                    float bx = ub ? bias[col] : 0.0f;
                    float by = ub ? bias[col + 1] : 0.0f;
                    float v00 = acc[mi][ni][0] + bx, v01 = acc[mi][ni][1] + by;
                    float v10 = acc[mi][ni][2] + bx, v11 = acc[mi][ni][3] + by;
                    if (MODE == 1) {
                        __half* c0 = (__half*)Cz + (size_t)row * ldc;
                        __half* c1 = (__half*)Cz + (size_t)(row + 8) * ldc;
                        *(__half2*)(c0 + col) = __floats2half2_rn(v00, v01);
                        *(__half2*)(c1 + col) = __floats2half2_rn(v10, v11);
                    } else {
                        float* c0 = (float*)Cz + (size_t)row * ldc;
                        float* c1 = (float*)Cz + (size_t)(row + 8) * ldc;
                        *(float2*)(c0 + col) = make_float2(v00, v01);
                        *(float2*)(c1 + col) = make_float2(v10, v11);
                    }
                }
            }
        }
    }
}

// ======================= prep_main: winF + LayerNorm ========================
__global__ __launch_bounds__(384) void prep_main_kernel(
    const float* __restrict__ W_in,
    const float* __restrict__ x,
    const float* __restrict__ ln_g,
    const float* __restrict__ ln_b)
{
    __shared__ float sh[512];
    const int blk = blockIdx.x;
    const int tid = threadIdx.x;

    if (blk < PM_WIN) {
        int idx = blk * 384 + tid;
        int n, k; bfh_inv(idx, 48, n, k);
        g_winF[idx] = __float2half_rn(W_in[(size_t)k * EE + n]);
        return;
    }
    int row = blk - PM_WIN;
    const float2* xr = (const float2*)(x + (size_t)row * DM);
    float2 v = xr[tid];
    if (tid < 128) sh[384 + tid] = 0.0f;
    sh[tid] = v.x + v.y;
    __syncthreads();
    for (int off = 256; off > 0; off >>= 1) {
        if (tid < off) sh[tid] += sh[tid + off];
        __syncthreads();
    }
    float mu = sh[0] * (1.0f / DM);
    __syncthreads();
    float dx = v.x - mu, dy = v.y - mu;
    sh[tid] = dx * dx + dy * dy;
    __syncthreads();
    for (int off = 256; off > 0; off >>= 1) {
        if (tid < off) sh[tid] += sh[tid + off];
        __syncthreads();
    }
    float rstd = rsqrtf(sh[0] * (1.0f / DM) + LN_EPS);
    float2 gg = ((const float2*)ln_g)[tid];
    float2 bb = ((const float2*)ln_b)[tid];
    float h0 = dx * rstd * gg.x + bb.x;
    float h1 = dy * rstd * gg.y + bb.y;
    *(__half2*)(g_xn + afh_idx(row, 2 * tid, 48)) = __floats2half2_rn(h0, h1);
}

// ======================= prep_side: other weights + zero pad ================
__global__ __launch_bounds__(384) void prep_side_kernel(
    const float* __restrict__ W_out,
    const float* __restrict__ W_xp,
    const float* __restrict__ W_dt,
    const float* __restrict__ W_us,
    const float* __restrict__ b_xp,
    const float* __restrict__ b_dt,
    const float* __restrict__ b_us,
    const float* __restrict__ b_out)
{
    __shared__ float red[8][16][32];
    const int blk = blockIdx.x;
    const int tid = threadIdx.x;

    if (blk < PS_WOL) {
        int idx = blk * 384 + tid;
        int n, k; bfh_inv(idx, 48, n, k);
        g_wolF[idx] = __float2half_rn(W_out[(size_t)k * DM + n]);
    } else if (blk < PS_XPL) {
        int idx = (blk - PS_WOL) * 384 + tid;
        int r, k; afh_inv(idx, 48, r, k);
        g_xplF[idx] = __float2half_rn(W_xp[(size_t)r * (DM + DS) + k]);
    } else if (blk < PS_WPS) {
        int idx = (blk - PS_XPL) * 384 + tid;
        int n, k; bfh_inv(idx, 96, n, k);
        float v = (n < DS)     ? W_xp[(size_t)k * (DM + DS) + DM + n]
                : (n < 2 * DS) ? W_dt[(size_t)k * DS + (n - DS)]
                : 0.0f;
        g_wpsF[idx] = __float2half_rn(v);
        if (blk == PS_XPL && tid < 32)
            g_bias32[tid] = (tid < DS) ? b_xp[DM + tid] : b_dt[tid - DS];
    } else if (blk < PS_WUS2) {
        int bb = blk - PS_WPS;
        if (tid < 256) {
            int n = bb * 32 + (tid & 31);
            int chunk = tid >> 5;
            float acc[16];
            #pragma unroll
            for (int s = 0; s < 16; s++) acc[s] = 0.0f;
            for (int j = chunk * 96; j < chunk * 96 + 96; j++) {
                float wo = W_out[(size_t)j * DM + n];
                #pragma unroll
                for (int s = 0; s < 16; s++)
                    acc[s] = fmaf(W_us[(size_t)s * DM + j], wo, acc[s]);
            }
            #pragma unroll
            for (int s = 0; s < 16; s++) red[chunk][s][tid & 31] = acc[s];
        }
        __syncthreads();
        for (int o = tid; o < 512; o += 384) {
            int s = o >> 5, ln = o & 31;
            float t = 0.0f;
            #pragma unroll
            for (int c = 0; c < 8; c++) t += red[c][s][ln];
            int nn = bb * 32 + ln;
            g_comboF[bfh_idx(nn, EE + s,          KC_CAT)] = __float2half_rn(t);
            g_comboF[bfh_idx(nn, EE + DS + s,     KC_CAT)] = __half(0.0f);
            g_comboF[bfh_idx(nn, EE + 2 * DS + s, KC_CAT)] = __half(0.0f);
            g_comboF[bfh_idx(nn, EE + 3 * DS + s, KC_CAT)] = __half(0.0f);
        }
    } else if (blk < PS_CB) {
        int n = (blk - PS_WUS2) * 384 + tid;
        if (n < DM) {
            float acc = b_out[n];
            for (int j = 0; j < DM; j++)
                acc = fmaf(b_xp[j] + b_us[j], W_out[(size_t)j * DM + n], acc);
            g_cbias[n] = acc;
        }
    } else {
        int idx = (blk - PS_CB) * 384 + tid;   // < 512*3*256
        int panel = idx / 768;
        int rem = idx % 768;
        int kb = 97 + (rem >> 8);
        g_cat[((size_t)panel * KC_CAT + kb) * 256 + (rem & 255)] = __half(0.0f);
    }
}

// ======================= depthwise conv + SiLU (per batch half) =============
__global__ void conv_silu_kernel(const float* __restrict__ b_conv,
                                 const float* __restrict__ W_conv,
                                 int row_base) {
    int idx = blockIdx.x * blockDim.x + threadIdx.x;
    if (idx >= (HROWS / 8) * (EE / 2)) return;
    int ep = idx % (EE / 2);
    int e0 = ep * 2;
    int r0 = row_base + (idx / (EE / 2)) * 8;
    int l0 = r0 % Lseq;
    const __half2* xin2 = (const __half2*)g_xin;

    float2 xa[11];
    #pragma unroll
    for (int j = 0; j < 3; j++) {
        if (l0 >= 3 - j) xa[j] = __half22float2(xin2[(size_t)(r0 - 3 + j) * (EE/2) + ep]);
        else             xa[j] = make_float2(0.f, 0.f);
    }
    #pragma unroll
    for (int j = 3; j < 11; j++)
        xa[j] = __half22float2(xin2[(size_t)(r0 - 3 + j) * (EE/2) + ep]);

    float4 wA = *(const float4*)(W_conv + e0 * 4);
    float4 wB = *(const float4*)(W_conv + e0 * 4 + 4);
    float bc0 = b_conv[e0], bc1 = b_conv[e0 + 1];

    __half* outb = g_cat + afh_idx(r0, e0, KC_CAT);
    #pragma unroll
    for (int i = 0; i < 8; i++) {
        float sx = bc0 + xa[i].x * wA.x + xa[i+1].x * wA.y + xa[i+2].x * wA.z + xa[i+3].x * wA.w;
        float sy = bc1 + xa[i].y * wB.x + xa[i+1].y * wB.y + xa[i+2].y * wB.z + xa[i+3].y * wB.w;
        float ax = sx / (1.0f + __expf(-sx));
        float ay = sy / (1.0f + __expf(-sy));
        *(__half2*)(outb + i * 32) = __floats2half2_rn(ax, ay);
    }
}

// ======================= fused prescan + scan + us (per batch) ==============
__global__ __launch_bounds__(256) void scan_kernel(int batch) {
    int s = blockIdx.x;              // 0..15
    int t = threadIdx.x;
    __shared__ float sA[256], sB[256];
    float A = 1.0f, Bl = 0.0f;
    int base = batch * Lseq;
    #pragma unroll 4
    for (int i = 0; i < 16; i++) {
        size_t rofs = (size_t)(base + t * 16 + i);
        float ds = 0.0f, dtraw = 0.0f;
        #pragma unroll
        for (int z = 0; z < XD_ZS; z++) {
            ds    += g_xd[(size_t)z * NROWS * 32 + rofs * 32 + s];
            dtraw += g_xd[(size_t)z * NROWS * 32 + rofs * 32 + 16 + s];
        }
        float dt = fmaxf(dtraw, 0.0f) + log1pf(__expf(-fabsf(dtraw)));
        float bt = ds * __expf(-0.5f * dt);
        g_dt[rofs * DS + s] = dt;
        g_bt[rofs * DS + s] = bt;
        float a = __expf(-dt);
        Bl = a * Bl + bt;
        A = a * A;
    }
    sA[t] = A; sB[t] = Bl;
    __syncthreads();
    for (int offp = 1; offp < 256; offp <<= 1) {
        float pA = 0.f, pB = 0.f;
        bool has = (t >= offp);
        if (has) { pA = sA[t - offp]; pB = sB[t - offp]; }
        __syncthreads();
        if (has) { sB[t] = sA[t] * pB + sB[t]; sA[t] = sA[t] * pA; }
        __syncthreads();
    }
    float v = (t == 0) ? 0.0f : sB[t - 1];
    for (int i = 0; i < 16; i++) {
        int l = t * 16 + i;
        int row = base + l;
        size_t off = (size_t)row * DS + s;
        float dt = g_dt[off];
        float bt = g_bt[off];
        v = __expf(-dt) * v + bt;
        float kf = (float)(Lseq - 1 - l);
        float denom = expm1f(-dt);
        if (denom > -1e-30f) denom = -1e-30f;
        float us = __expf(-kf * dt) * v + bt * expm1f(-kf * dt) / denom;
        g_cat[afh_idx(row, EE + s, KC_CAT)] = __float2half_rn(us);
    }
}

// ======================= launch =============================================
extern "C" void kernel_launch(void* const* d_in, const int* in_sizes, int n_in,
                              void* d_out, int out_size) {
    const float* x      = (const float*)d_in[0];
    const float* ln_g   = (const float*)d_in[1];
    const float* ln_b   = (const float*)d_in[2];
    const float* W_in   = (const float*)d_in[3];
    const float* b_in   = (const float*)d_in[4];
    const float* W_conv = (const float*)d_in[5];
    const float* b_conv = (const float*)d_in[6];
    const float* W_xp   = (const float*)d_in[7];
    const float* b_xp   = (const float*)d_in[8];
    const float* W_dt   = (const float*)d_in[9];
    const float* b_dt   = (const float*)d_in[10];
    const float* W_us   = (const float*)d_in[11];
    const float* b_us   = (const float*)d_in[12];
    const float* W_out  = (const float*)d_in[13];
    const float* b_out  = (const float*)d_in[14];
    float* out = (float*)d_out;

    __half *xn, *xin, *cat, *winF, *wpsF, *xplF, *wolF, *comboF;
    float *xd, *bias32, *cbias;
    cudaGetSymbolAddress((void**)&xn,     g_xn);
    cudaGetSymbolAddress((void**)&xin,    g_xin);
    cudaGetSymbolAddress((void**)&cat,    g_cat);
    cudaGetSymbolAddress((void**)&xd,     g_xd);
    cudaGetSymbolAddress((void**)&bias32, g_bias32);
    cudaGetSymbolAddress((void**)&cbias,  g_cbias);
    cudaGetSymbolAddress((void**)&winF,   g_winF);
    cudaGetSymbolAddress((void**)&wpsF,   g_wpsF);
    cudaGetSymbolAddress((void**)&xplF,   g_xplF);
    cudaGetSymbolAddress((void**)&wolF,   g_wolF);
    cudaGetSymbolAddress((void**)&comboF, g_comboF);

    static cudaStream_t s1 = nullptr, s2 = nullptr;
    static cudaEvent_t evFork = nullptr, evSide = nullptr;
    static cudaEvent_t evG1b0 = nullptr, evG1b1 = nullptr;
    static cudaEvent_t evScan0 = nullptr, evScan1 = nullptr;
    if (!s1) {
        cudaStreamCreateWithFlags(&s1, cudaStreamNonBlocking);
        cudaStreamCreateWithFlags(&s2, cudaStreamNonBlocking);
        cudaEventCreateWithFlags(&evFork,  cudaEventDisableTiming);
        cudaEventCreateWithFlags(&evSide,  cudaEventDisableTiming);
        cudaEventCreateWithFlags(&evG1b0,  cudaEventDisableTiming);
        cudaEventCreateWithFlags(&evG1b1,  cudaEventDisableTiming);
        cudaEventCreateWithFlags(&evScan0, cudaEventDisableTiming);
        cudaEventCreateWithFlags(&evScan1, cudaEventDisableTiming);
        cudaFuncSetAttribute(gemm_f16_kernel<0>, cudaFuncAttributeMaxDynamicSharedMemorySize, GEMM_SMEM);
        cudaFuncSetAttribute(gemm_f16_kernel<1>, cudaFuncAttributeMaxDynamicSharedMemorySize, GEMM_SMEM);
        cudaFuncSetAttribute(gemm_f16_kernel<2>, cudaFuncAttributeMaxDynamicSharedMemorySize, GEMM_SMEM);
    }

    const size_t XD_STRIDE = (size_t)NROWS * 32 * sizeof(float);

    // fork side stream
    cudaEventRecord(evFork, 0);
    cudaStreamWaitEvent(s1, evFork, 0);
    prep_side_kernel<<<PS_ZC, 384, 0, s1>>>(W_out, W_xp, W_dt, W_us,
                                            b_xp, b_dt, b_us, b_out);
    gemm_f16_kernel<2><<<dim3(DM/128, EE/128, 1), 256, GEMM_SMEM, s1>>>(
        xplF, 48, wolF, nullptr, comboF, 0, DM, DM, W_out, 0, 0);
    cudaEventRecord(evSide, s1);

    // main: prep (winF + all LN rows)
    prep_main_kernel<<<PM_TOTAL, 384>>>(W_in, x, ln_g, ln_b);

    // main: gemm1 batch 0
    gemm_f16_kernel<1><<<dim3(EE/128, HROWS/128, 1), 256, GEMM_SMEM>>>(
        xn, 48, winF, b_in, xin, EE, EE, DM, nullptr, 0, 0);
    cudaEventRecord(evG1b0, 0);

    // main: gemm1 batch 1
    gemm_f16_kernel<1><<<dim3(EE/128, HROWS/128, 1), 256, GEMM_SMEM>>>(
        xn, 48, winF, b_in, xin, EE, EE, DM, nullptr, 0, HROWS);
    cudaEventRecord(evG1b1, 0);

    // s2: batch-0 chain (conv -> small -> scan)
    cudaStreamWaitEvent(s2, evG1b0, 0);
    conv_silu_kernel<<<((HROWS/8) * (EE/2) + 255) / 256, 256, 0, s2>>>(
        b_conv, W_conv, 0);
    cudaStreamWaitEvent(s2, evSide, 0);
    gemm_f16_kernel<0><<<dim3(1, HROWS/128, XD_ZS), 256, GEMM_SMEM, s2>>>(
        cat, KC_CAT, wpsF, bias32, xd, 32, 32, EE, nullptr, XD_STRIDE, 0);
    scan_kernel<<<DS, 256, 0, s2>>>(0);
    cudaEventRecord(evScan0, s2);

    // s2: batch-1 chain
    cudaStreamWaitEvent(s2, evG1b1, 0);
    conv_silu_kernel<<<((HROWS/8) * (EE/2) + 255) / 256, 256, 0, s2>>>(
        b_conv, W_conv, HROWS);
    gemm_f16_kernel<0><<<dim3(1, HROWS/128, XD_ZS), 256, GEMM_SMEM, s2>>>(
        cat, KC_CAT, wpsF, bias32, xd, 32, 32, EE, nullptr, XD_STRIDE, HROWS);
    scan_kernel<<<DS, 256, 0, s2>>>(1);
    cudaEventRecord(evScan1, s2);

    // main: final batch 0 (after its scan)
    cudaStreamWaitEvent(0, evScan0, 0);
    gemm_f16_kernel<0><<<dim3(DM/128, HROWS/128, 1), 256, GEMM_SMEM>>>(
        cat, KC_CAT, comboF, cbias, out, DM, DM, KCAT, nullptr, 0, 0);

    // main: final batch 1
    cudaStreamWaitEvent(0, evScan1, 0);
    gemm_f16_kernel<0><<<dim3(DM/128, HROWS/128, 1), 256, GEMM_SMEM>>>(
        cat, KC_CAT, comboF, cbias, out, DM, DM, KCAT, nullptr, 0, HROWS);
}